// round 1
// baseline (speedup 1.0000x reference)
#include <cuda_runtime.h>
#include <cstdint>

#define NN 50000
#define NE 600000
#define NG 64

// ---------------- scratch (no allocations allowed) ----------------
__device__ float g_agg[(size_t)NN * 128];
__device__ float g_mid[(size_t)NN * 128];
__device__ float g_h  [(size_t)NN * 128];
__device__ float g_pool[NG * 128];
__device__ float g_cnt[NG];
__device__ int   g_is64;

// ---------------- helpers ----------------
__device__ __forceinline__ void red_add_v4(float* addr, float a, float b, float c, float d) {
    asm volatile("red.global.add.v4.f32 [%0], {%1,%2,%3,%4};"
                 :: "l"(addr), "f"(a), "f"(b), "f"(c), "f"(d) : "memory");
}

__device__ __forceinline__ long long load_idx(const void* p, long long i, int is64) {
    if (is64) return ((const long long*)p)[i];
    return (long long)((const int*)p)[i];
}

// Detect int64 vs int32 index buffers: for int64 non-negative values < 2^31,
// every odd 32-bit word is zero. For int32 (random node ids), essentially never.
__global__ void detect_kernel(const int* ei32) {
    int v = ei32[2 * threadIdx.x + 1] | ei32[2 * (threadIdx.x + 32) + 1];
    unsigned b = __ballot_sync(0xffffffffu, v != 0);
    if (threadIdx.x == 0) g_is64 = (b == 0) ? 1 : 0;
}

__global__ void zero_kernel(float* p, long long n4) {
    long long i = (long long)blockIdx.x * blockDim.x + threadIdx.x;
    if (i < n4) ((float4*)p)[i] = make_float4(0.f, 0.f, 0.f, 0.f);
}

// ---------------- edge message + scatter-add ----------------
// msg = relu(x[src] + edge_attr @ ew + eb), agg[dst] += msg
template <int CH>
__global__ void edge_msg_kernel(const float* __restrict__ xf, const void* __restrict__ ei,
                                const float* __restrict__ attr,
                                const float* __restrict__ ew, const float* __restrict__ eb,
                                float* __restrict__ agg) {
    const int TPE = CH / 4;
    long long idx = (long long)blockIdx.x * blockDim.x + threadIdx.x;
    if (idx >= (long long)NE * TPE) return;
    long long e = idx / TPE;
    int c4 = (int)(idx % TPE) * 4;
    int is64 = g_is64;
    long long src = load_idx(ei, e, is64);
    long long dst = load_idx(ei, (long long)NE + e, is64);
    float a0 = __ldg(&attr[e * 3 + 0]);
    float a1 = __ldg(&attr[e * 3 + 1]);
    float a2 = __ldg(&attr[e * 3 + 2]);
    float4 x4 = *(const float4*)&xf[src * CH + c4];
    float m[4] = {x4.x, x4.y, x4.z, x4.w};
#pragma unroll
    for (int j = 0; j < 4; j++) {
        int c = c4 + j;
        float ev = __ldg(&eb[c]) + a0 * __ldg(&ew[c]) + a1 * __ldg(&ew[CH + c]) + a2 * __ldg(&ew[2 * CH + c]);
        m[j] = fmaxf(m[j] + ev, 0.f);
    }
    red_add_v4(&agg[dst * CH + c4], m[0], m[1], m[2], m[3]);
}

// ---------------- fused node MLP GEMM ----------------
// C[N,128] = relu( (A0 (+ A1)) [N,K] @ W[K,128] + bias[128] )
// 128x128 block tile, BK=16, 256 threads, 8x8 register micro-tile.
__global__ __launch_bounds__(256, 2) void mlp_gemm_kernel(
    const float* __restrict__ A0, const float* __restrict__ A1,
    const float* __restrict__ W, const float* __restrict__ bias,
    float* __restrict__ C, int K) {
    __shared__ float As[16][128];
    __shared__ float Ws[16][128];
    const int tid = threadIdx.x;
    const int block_row = blockIdx.x * 128;
    const int trow = (tid >> 4) * 8;
    const int tcol = (tid & 15) * 8;
    float acc[8][8];
#pragma unroll
    for (int i = 0; i < 8; i++)
#pragma unroll
        for (int j = 0; j < 8; j++) acc[i][j] = 0.f;

    for (int k0 = 0; k0 < K; k0 += 16) {
        // stage A tile (transposed to [k][row]), fused elementwise add of A1
#pragma unroll
        for (int i = 0; i < 2; i++) {
            int idx = tid + i * 256;       // 0..511
            int r = idx >> 2;              // row in tile 0..127
            int kc = (idx & 3) * 4;        // k offset 0..12
            int gr = block_row + r;
            float4 v = make_float4(0.f, 0.f, 0.f, 0.f);
            if (gr < NN) {
                v = *(const float4*)&A0[(long long)gr * K + k0 + kc];
                if (A1) {
                    float4 u = *(const float4*)&A1[(long long)gr * K + k0 + kc];
                    v.x += u.x; v.y += u.y; v.z += u.z; v.w += u.w;
                }
            }
            As[kc + 0][r] = v.x; As[kc + 1][r] = v.y;
            As[kc + 2][r] = v.z; As[kc + 3][r] = v.w;
        }
        // stage W tile [k][col]
#pragma unroll
        for (int i = 0; i < 2; i++) {
            int idx = tid + i * 256;
            int r = idx >> 5;              // k row 0..15
            int cc = (idx & 31) * 4;       // col 0..124
            *(float4*)&Ws[r][cc] = *(const float4*)&W[(long long)(k0 + r) * 128 + cc];
        }
        __syncthreads();
#pragma unroll
        for (int k = 0; k < 16; k++) {
            float a[8], w[8];
            *(float4*)&a[0] = *(const float4*)&As[k][trow];
            *(float4*)&a[4] = *(const float4*)&As[k][trow + 4];
            *(float4*)&w[0] = *(const float4*)&Ws[k][tcol];
            *(float4*)&w[4] = *(const float4*)&Ws[k][tcol + 4];
#pragma unroll
            for (int i = 0; i < 8; i++)
#pragma unroll
                for (int j = 0; j < 8; j++)
                    acc[i][j] = fmaf(a[i], w[j], acc[i][j]);
        }
        __syncthreads();
    }
#pragma unroll
    for (int i = 0; i < 8; i++) {
        int gr = block_row + trow + i;
        if (gr < NN) {
#pragma unroll
            for (int j = 0; j < 8; j += 4) {
                float4 o;
                o.x = fmaxf(acc[i][j + 0] + bias[tcol + j + 0], 0.f);
                o.y = fmaxf(acc[i][j + 1] + bias[tcol + j + 1], 0.f);
                o.z = fmaxf(acc[i][j + 2] + bias[tcol + j + 2], 0.f);
                o.w = fmaxf(acc[i][j + 3] + bias[tcol + j + 3], 0.f);
                *(float4*)&C[(long long)gr * 128 + tcol + j] = o;
            }
        }
    }
}

// ---------------- global mean pool ----------------
__global__ void pool_kernel(const float* __restrict__ h, const void* __restrict__ batch,
                            float* __restrict__ pool, float* __restrict__ cnt) {
    long long idx = (long long)blockIdx.x * blockDim.x + threadIdx.x;
    if (idx >= (long long)NN * 32) return;
    long long n = idx >> 5;
    int c4 = (int)(idx & 31) * 4;
    long long g = load_idx(batch, n, g_is64);
    float4 v = *(const float4*)&h[n * 128 + c4];
    red_add_v4(&pool[g * 128 + c4], v.x, v.y, v.z, v.w);
    if (c4 == 0) atomicAdd(&cnt[g], 1.0f);
}

__global__ void finalize_kernel(const float* __restrict__ pool, const float* __restrict__ cnt,
                                float* __restrict__ out) {
    int i = blockIdx.x * blockDim.x + threadIdx.x;
    if (i < NG * 128) out[i] = pool[i] / fmaxf(cnt[i >> 7], 1.0f);
}

// ---------------- launch ----------------
extern "C" void kernel_launch(void* const* d_in, const int* in_sizes, int n_in,
                              void* d_out, int out_size) {
    const float* x     = (const float*)d_in[0];
    const void*  ei    = d_in[1];
    const float* attr  = (const float*)d_in[2];
    const void*  batch = d_in[3];
    const float* el1_w = (const float*)d_in[4];
    const float* el1_b = (const float*)d_in[5];
    const float* w1a   = (const float*)d_in[6];
    const float* b1a   = (const float*)d_in[7];
    const float* w1b   = (const float*)d_in[8];
    const float* b1b   = (const float*)d_in[9];
    const float* el2_w = (const float*)d_in[10];
    const float* el2_b = (const float*)d_in[11];
    const float* w2a   = (const float*)d_in[12];
    const float* b2a   = (const float*)d_in[13];
    const float* w2b   = (const float*)d_in[14];
    const float* b2b   = (const float*)d_in[15];
    float* out = (float*)d_out;

    float *agg, *mid, *h, *pool, *cnt;
    cudaGetSymbolAddress((void**)&agg,  g_agg);
    cudaGetSymbolAddress((void**)&mid,  g_mid);
    cudaGetSymbolAddress((void**)&h,    g_h);
    cudaGetSymbolAddress((void**)&pool, g_pool);
    cudaGetSymbolAddress((void**)&cnt,  g_cnt);

    detect_kernel<<<1, 32>>>((const int*)ei);

    const long long n4 = (long long)NN * 128 / 4;
    const int zgrid = (int)((n4 + 255) / 256);
    const int ggrid = (NN + 127) / 128;

    // ---- layer 1 ----
    zero_kernel<<<zgrid, 256>>>(agg, n4);
    {
        long long t = (long long)NE * 16;
        edge_msg_kernel<64><<<(int)((t + 255) / 256), 256>>>(x, ei, attr, el1_w, el1_b, agg);
    }
    mlp_gemm_kernel<<<ggrid, 256>>>(x,   agg,     w1a, b1a, mid, 64);
    mlp_gemm_kernel<<<ggrid, 256>>>(mid, nullptr, w1b, b1b, h,   128);

    // ---- layer 2 ----
    zero_kernel<<<zgrid, 256>>>(agg, n4);
    {
        long long t = (long long)NE * 32;
        edge_msg_kernel<128><<<(int)((t + 255) / 256), 256>>>(h, ei, attr, el2_w, el2_b, agg);
    }
    mlp_gemm_kernel<<<ggrid, 256>>>(h,   agg,     w2a, b2a, mid, 128);
    mlp_gemm_kernel<<<ggrid, 256>>>(mid, nullptr, w2b, b2b, h,   128);

    // ---- global mean pool ----
    zero_kernel<<<(NG * 128 / 4 + 255) / 256, 256>>>(pool, NG * 128 / 4);
    zero_kernel<<<1, 16>>>(cnt, NG / 4);
    {
        long long t = (long long)NN * 32;
        pool_kernel<<<(int)((t + 255) / 256), 256>>>(h, batch, pool, cnt);
    }
    finalize_kernel<<<(NG * 128 + 255) / 256, 256>>>(pool, cnt, out);
}

// round 2
// speedup vs baseline: 1.0491x; 1.0491x over previous
#include <cuda_runtime.h>
#include <cstdint>

#define NN 50000
#define NE 600000
#define NG 64

// ---------------- scratch (no allocations allowed) ----------------
__device__ float g_agg[(size_t)NN * 128];
__device__ float g_mid[(size_t)NN * 128];
__device__ float g_h  [(size_t)NN * 128];
__device__ float g_pool[NG * 128];
__device__ float g_cnt[NG];
__device__ int   g_is64;

// ---------------- helpers ----------------
__device__ __forceinline__ void red_add_v4(float* addr, float a, float b, float c, float d) {
    asm volatile("red.global.add.v4.f32 [%0], {%1,%2,%3,%4};"
                 :: "l"(addr), "f"(a), "f"(b), "f"(c), "f"(d) : "memory");
}

__device__ __forceinline__ long long load_idx(const void* p, long long i, int is64) {
    if (is64) return ((const long long*)p)[i];
    return (long long)((const int*)p)[i];
}

// packed f32x2 FMA: d = a*b + d  (SASS FFMA2, only reachable via PTX)
__device__ __forceinline__ void ffma2(unsigned long long& d,
                                      unsigned long long a, unsigned long long b) {
    asm("fma.rn.f32x2 %0, %1, %2, %0;" : "+l"(d) : "l"(a), "l"(b));
}
__device__ __forceinline__ unsigned long long pack2(float x) {
    unsigned long long r;
    asm("mov.b64 %0, {%1, %1};" : "=l"(r) : "f"(x));
    return r;
}

// Detect int64 vs int32 index buffers.
__global__ void detect_kernel(const int* ei32) {
    int v = ei32[2 * threadIdx.x + 1] | ei32[2 * (threadIdx.x + 32) + 1];
    unsigned b = __ballot_sync(0xffffffffu, v != 0);
    if (threadIdx.x == 0) g_is64 = (b == 0) ? 1 : 0;
}

__global__ void zero_kernel(float* p, long long n4) {
    long long i = (long long)blockIdx.x * blockDim.x + threadIdx.x;
    if (i < n4) ((float4*)p)[i] = make_float4(0.f, 0.f, 0.f, 0.f);
}

// agg <- src  (seed aggregation with (1+eps)*x, eps=0)
__global__ void copy_kernel(const float* __restrict__ src, float* __restrict__ dst, long long n4) {
    long long i = (long long)blockIdx.x * blockDim.x + threadIdx.x;
    if (i < n4) ((float4*)dst)[i] = ((const float4*)src)[i];
}

// ---------------- edge message + scatter-add ----------------
// agg[dst] += relu(x[src] + edge_attr @ ew + eb)
template <int CH>
__global__ void edge_msg_kernel(const float* __restrict__ xf, const void* __restrict__ ei,
                                const float* __restrict__ attr,
                                const float* __restrict__ ew, const float* __restrict__ eb,
                                float* __restrict__ agg) {
    const int TPE = CH / 4;
    long long idx = (long long)blockIdx.x * blockDim.x + threadIdx.x;
    if (idx >= (long long)NE * TPE) return;
    long long e = idx / TPE;
    int c4 = (int)(idx % TPE) * 4;
    int is64 = g_is64;
    long long src = load_idx(ei, e, is64);
    long long dst = load_idx(ei, (long long)NE + e, is64);
    float a0 = __ldg(&attr[e * 3 + 0]);
    float a1 = __ldg(&attr[e * 3 + 1]);
    float a2 = __ldg(&attr[e * 3 + 2]);
    float4 x4 = *(const float4*)&xf[src * CH + c4];
    float m[4] = {x4.x, x4.y, x4.z, x4.w};
#pragma unroll
    for (int j = 0; j < 4; j++) {
        int c = c4 + j;
        float ev = __ldg(&eb[c]) + a0 * __ldg(&ew[c]) + a1 * __ldg(&ew[CH + c]) + a2 * __ldg(&ew[2 * CH + c]);
        m[j] = fmaxf(m[j] + ev, 0.f);
    }
    red_add_v4(&agg[dst * CH + c4], m[0], m[1], m[2], m[3]);
}

// ---------------- node MLP GEMM (FFMA2 inner loop) ----------------
// C[N,128] = relu( A[N,K] @ W[K,128] + bias[128] )
// 128x128 block tile, BK=16, 256 threads, 8x8 register micro-tile as 8x4 f32x2.
__global__ __launch_bounds__(256, 2) void mlp_gemm_kernel(
    const float* __restrict__ A, const float* __restrict__ W,
    const float* __restrict__ bias, float* __restrict__ C, int K) {
    __shared__ float As[16][128];
    __shared__ float Ws[16][128];
    const int tid = threadIdx.x;
    const int block_row = blockIdx.x * 128;
    const int trow = (tid >> 4) * 8;
    const int tcol = (tid & 15) * 8;
    unsigned long long acc[8][4];
#pragma unroll
    for (int i = 0; i < 8; i++)
#pragma unroll
        for (int j = 0; j < 4; j++) acc[i][j] = 0ull;

    for (int k0 = 0; k0 < K; k0 += 16) {
        // stage A tile transposed to [k][row]
#pragma unroll
        for (int i = 0; i < 2; i++) {
            int idx = tid + i * 256;       // 0..511
            int r = idx >> 2;              // row in tile 0..127
            int kc = (idx & 3) * 4;        // k offset 0..12
            int gr = block_row + r;
            float4 v = make_float4(0.f, 0.f, 0.f, 0.f);
            if (gr < NN) v = *(const float4*)&A[(long long)gr * K + k0 + kc];
            As[kc + 0][r] = v.x; As[kc + 1][r] = v.y;
            As[kc + 2][r] = v.z; As[kc + 3][r] = v.w;
        }
        // stage W tile [k][col]
#pragma unroll
        for (int i = 0; i < 2; i++) {
            int idx = tid + i * 256;
            int r = idx >> 5;              // k row 0..15
            int cc = (idx & 31) * 4;       // col 0..124
            *(float4*)&Ws[r][cc] = *(const float4*)&W[(long long)(k0 + r) * 128 + cc];
        }
        __syncthreads();
#pragma unroll
        for (int k = 0; k < 16; k++) {
            float a_[8];
            *(float4*)&a_[0] = *(const float4*)&As[k][trow];
            *(float4*)&a_[4] = *(const float4*)&As[k][trow + 4];
            ulonglong2 wA = *(const ulonglong2*)&Ws[k][tcol];
            ulonglong2 wB = *(const ulonglong2*)&Ws[k][tcol + 4];
            unsigned long long w_[4] = {wA.x, wA.y, wB.x, wB.y};
#pragma unroll
            for (int i = 0; i < 8; i++) {
                unsigned long long a2 = pack2(a_[i]);
#pragma unroll
                for (int j = 0; j < 4; j++) ffma2(acc[i][j], a2, w_[j]);
            }
        }
        __syncthreads();
    }
    // epilogue: bias + relu
    float bv[8];
    *(float4*)&bv[0] = *(const float4*)&bias[tcol];
    *(float4*)&bv[4] = *(const float4*)&bias[tcol + 4];
#pragma unroll
    for (int i = 0; i < 8; i++) {
        int gr = block_row + trow + i;
        if (gr < NN) {
            union { unsigned long long u; float2 f; } cv;
            float o[8];
#pragma unroll
            for (int j = 0; j < 4; j++) {
                cv.u = acc[i][j];
                o[2 * j + 0] = fmaxf(cv.f.x + bv[2 * j + 0], 0.f);
                o[2 * j + 1] = fmaxf(cv.f.y + bv[2 * j + 1], 0.f);
            }
            *(float4*)&C[(long long)gr * 128 + tcol]     = *(float4*)&o[0];
            *(float4*)&C[(long long)gr * 128 + tcol + 4] = *(float4*)&o[4];
        }
    }
}

// ---------------- global mean pool ----------------
__global__ void pool_kernel(const float* __restrict__ h, const void* __restrict__ batch,
                            float* __restrict__ pool, float* __restrict__ cnt) {
    long long idx = (long long)blockIdx.x * blockDim.x + threadIdx.x;
    if (idx >= (long long)NN * 32) return;
    long long n = idx >> 5;
    int c4 = (int)(idx & 31) * 4;
    long long g = load_idx(batch, n, g_is64);
    float4 v = *(const float4*)&h[n * 128 + c4];
    red_add_v4(&pool[g * 128 + c4], v.x, v.y, v.z, v.w);
    if (c4 == 0) atomicAdd(&cnt[g], 1.0f);
}

__global__ void finalize_kernel(const float* __restrict__ pool, const float* __restrict__ cnt,
                                float* __restrict__ out) {
    int i = blockIdx.x * blockDim.x + threadIdx.x;
    if (i < NG * 128) out[i] = pool[i] / fmaxf(cnt[i >> 7], 1.0f);
}

// ---------------- launch ----------------
extern "C" void kernel_launch(void* const* d_in, const int* in_sizes, int n_in,
                              void* d_out, int out_size) {
    const float* x     = (const float*)d_in[0];
    const void*  ei    = d_in[1];
    const float* attr  = (const float*)d_in[2];
    const void*  batch = d_in[3];
    const float* el1_w = (const float*)d_in[4];
    const float* el1_b = (const float*)d_in[5];
    const float* w1a   = (const float*)d_in[6];
    const float* b1a   = (const float*)d_in[7];
    const float* w1b   = (const float*)d_in[8];
    const float* b1b   = (const float*)d_in[9];
    const float* el2_w = (const float*)d_in[10];
    const float* el2_b = (const float*)d_in[11];
    const float* w2a   = (const float*)d_in[12];
    const float* b2a   = (const float*)d_in[13];
    const float* w2b   = (const float*)d_in[14];
    const float* b2b   = (const float*)d_in[15];
    float* out = (float*)d_out;

    float *agg, *mid, *h, *pool, *cnt;
    cudaGetSymbolAddress((void**)&agg,  g_agg);
    cudaGetSymbolAddress((void**)&mid,  g_mid);
    cudaGetSymbolAddress((void**)&h,    g_h);
    cudaGetSymbolAddress((void**)&pool, g_pool);
    cudaGetSymbolAddress((void**)&cnt,  g_cnt);

    detect_kernel<<<1, 32>>>((const int*)ei);

    const int ggrid = (NN + 127) / 128;

    // ---- layer 1 (CH=64) ----
    {
        long long n4 = (long long)NN * 64 / 4;
        copy_kernel<<<(int)((n4 + 255) / 256), 256>>>(x, agg, n4);
        long long t = (long long)NE * 16;
        edge_msg_kernel<64><<<(int)((t + 255) / 256), 256>>>(x, ei, attr, el1_w, el1_b, agg);
    }
    mlp_gemm_kernel<<<ggrid, 256>>>(agg, w1a, b1a, mid, 64);
    mlp_gemm_kernel<<<ggrid, 256>>>(mid, w1b, b1b, h, 128);

    // ---- layer 2 (CH=128) ----
    {
        long long n4 = (long long)NN * 128 / 4;
        copy_kernel<<<(int)((n4 + 255) / 256), 256>>>(h, agg, n4);
        long long t = (long long)NE * 32;
        edge_msg_kernel<128><<<(int)((t + 255) / 256), 256>>>(h, ei, attr, el2_w, el2_b, agg);
    }
    mlp_gemm_kernel<<<ggrid, 256>>>(agg, w2a, b2a, mid, 128);
    mlp_gemm_kernel<<<ggrid, 256>>>(mid, w2b, b2b, h, 128);

    // ---- global mean pool ----
    zero_kernel<<<(NG * 128 / 4 + 255) / 256, 256>>>(pool, NG * 128 / 4);
    zero_kernel<<<1, 16>>>(cnt, NG / 4);
    {
        long long t = (long long)NN * 32;
        pool_kernel<<<(int)((t + 255) / 256), 256>>>(h, batch, pool, cnt);
    }
    finalize_kernel<<<(NG * 128 + 255) / 256, 256>>>(pool, cnt, out);
}

// round 4
// speedup vs baseline: 1.2713x; 1.2118x over previous
#include <cuda_runtime.h>
#include <cstdint>

#define NN 50000
#define NE 600000
#define NG 64

// ---------------- scratch (no allocations allowed) ----------------
__device__ float g_agg[(size_t)NN * 128];
__device__ float g_mid[(size_t)NN * 128];
__device__ float g_h  [(size_t)NN * 128];
__device__ float g_pool[NG * 128];
__device__ float g_cnt[NG];
__device__ int   g_is64;

// ---------------- helpers ----------------
__device__ __forceinline__ void red_add_v4(float* addr, float a, float b, float c, float d) {
    asm volatile("red.global.add.v4.f32 [%0], {%1,%2,%3,%4};"
                 :: "l"(addr), "f"(a), "f"(b), "f"(c), "f"(d) : "memory");
}
__device__ __forceinline__ long long load_idx(const void* p, long long i, int is64) {
    if (is64) return ((const long long*)p)[i];
    return (long long)((const int*)p)[i];
}
__device__ __forceinline__ uint32_t f2tf32(float x) {
    uint32_t r;
    asm("cvt.rna.tf32.f32 %0, %1;" : "=r"(r) : "f"(x));
    return r;
}
// tensor-core tf32 MMA (base ISA, lowers to HMMA on sm_10x)
__device__ __forceinline__ void mma16n8k8(float* c, const uint32_t* a, uint32_t b0, uint32_t b1) {
    asm volatile("mma.sync.aligned.m16n8k8.row.col.f32.tf32.tf32.f32 "
                 "{%0,%1,%2,%3}, {%4,%5,%6,%7}, {%8,%9}, {%0,%1,%2,%3};"
                 : "+f"(c[0]), "+f"(c[1]), "+f"(c[2]), "+f"(c[3])
                 : "r"(a[0]), "r"(a[1]), "r"(a[2]), "r"(a[3]), "r"(b0), "r"(b1));
}

__global__ void detect_kernel(const int* ei32) {
    int v = ei32[2 * threadIdx.x + 1] | ei32[2 * (threadIdx.x + 32) + 1];
    unsigned b = __ballot_sync(0xffffffffu, v != 0);
    if (threadIdx.x == 0) g_is64 = (b == 0) ? 1 : 0;
}
__global__ void zero_kernel(float* p, long long n4) {
    long long i = (long long)blockIdx.x * blockDim.x + threadIdx.x;
    if (i < n4) ((float4*)p)[i] = make_float4(0.f, 0.f, 0.f, 0.f);
}
__global__ void copy_kernel(const float* __restrict__ src, float* __restrict__ dst, long long n4) {
    long long i = (long long)blockIdx.x * blockDim.x + threadIdx.x;
    if (i < n4) ((float4*)dst)[i] = ((const float4*)src)[i];
}

// ---------------- edge message + scatter-add ----------------
// agg[dst] += relu(x[src] + edge_attr @ ew + eb)
template <int CH>
__global__ void edge_msg_kernel(const float* __restrict__ xf, const void* __restrict__ ei,
                                const float* __restrict__ attr,
                                const float* __restrict__ ew, const float* __restrict__ eb,
                                float* __restrict__ agg) {
    const int TPE = CH / 4;
    long long idx = (long long)blockIdx.x * blockDim.x + threadIdx.x;
    if (idx >= (long long)NE * TPE) return;
    long long e = idx / TPE;
    int c4 = (int)(idx % TPE) * 4;
    int is64 = g_is64;
    long long src = load_idx(ei, e, is64);
    long long dst = load_idx(ei, (long long)NE + e, is64);
    float a0 = __ldg(&attr[e * 3 + 0]);
    float a1 = __ldg(&attr[e * 3 + 1]);
    float a2 = __ldg(&attr[e * 3 + 2]);
    float4 x4 = *(const float4*)&xf[src * CH + c4];
    float m[4] = {x4.x, x4.y, x4.z, x4.w};
#pragma unroll
    for (int j = 0; j < 4; j++) {
        int c = c4 + j;
        float ev = __ldg(&eb[c]) + a0 * __ldg(&ew[c]) + a1 * __ldg(&ew[CH + c]) + a2 * __ldg(&ew[2 * CH + c]);
        m[j] = fmaxf(m[j] + ev, 0.f);
    }
    red_add_v4(&agg[dst * CH + c4], m[0], m[1], m[2], m[3]);
}

// ---------------- tf32 tensor-core GEMM via mma.sync ----------------
// C[N,128] = relu( A[N,K] @ W[K,128] + bias )
// 128x128 CTA tile, 8 warps, warp tile 32x64 (2x8 m16n8k8 frags), BK=16.
template <int K>
__global__ __launch_bounds__(256, 2) void mma_gemm_kernel(
    const float* __restrict__ A, const float* __restrict__ W,
    const float* __restrict__ bias, float* __restrict__ C) {
    __shared__ uint32_t As[128][20];   // [row][k], pad 20 -> conflict-free frag loads
    __shared__ uint32_t Ws[16][136];   // [k][n],  pad 136 -> conflict-free frag loads
    const int tid = threadIdx.x, lane = tid & 31, wid = tid >> 5;
    const int block_row = blockIdx.x * 128;
    const int rbase = (wid & 3) * 32;
    const int cbase = (wid >> 2) * 64;
    const int g4 = lane >> 2;          // groupID
    const int t4 = lane & 3;           // threadID in group

    float acc[2][8][4];
#pragma unroll
    for (int i = 0; i < 2; i++)
#pragma unroll
        for (int j = 0; j < 8; j++)
#pragma unroll
            for (int q = 0; q < 4; q++) acc[i][j][q] = 0.f;

    for (int k0 = 0; k0 < K; k0 += 16) {
        // stage A tile [128 rows][16 k] as tf32
#pragma unroll
        for (int i = 0; i < 2; i++) {
            int idx = tid + i * 256;       // 0..511
            int r = idx >> 2;              // 0..127
            int kc = (idx & 3) * 4;        // 0,4,8,12
            int gr = block_row + r;
            float4 v = make_float4(0.f, 0.f, 0.f, 0.f);
            if (gr < NN) v = *(const float4*)&A[(long long)gr * K + k0 + kc];
            *(uint4*)&As[r][kc] = make_uint4(f2tf32(v.x), f2tf32(v.y), f2tf32(v.z), f2tf32(v.w));
        }
        // stage W tile [16 k][128 n] as tf32
#pragma unroll
        for (int i = 0; i < 2; i++) {
            int idx = tid + i * 256;
            int r = idx >> 5;              // 0..15
            int cc = (idx & 31) * 4;       // 0..124
            float4 v = *(const float4*)&W[(long long)(k0 + r) * 128 + cc];
            *(uint4*)&Ws[r][cc] = make_uint4(f2tf32(v.x), f2tf32(v.y), f2tf32(v.z), f2tf32(v.w));
        }
        __syncthreads();
#pragma unroll
        for (int ks = 0; ks < 2; ks++) {
            const int kk = ks * 8;
            uint32_t a[2][4];
#pragma unroll
            for (int i = 0; i < 2; i++) {
                int r = rbase + i * 16 + g4;
                a[i][0] = As[r][kk + t4];
                a[i][1] = As[r + 8][kk + t4];
                a[i][2] = As[r][kk + t4 + 4];
                a[i][3] = As[r + 8][kk + t4 + 4];
            }
#pragma unroll
            for (int j = 0; j < 8; j++) {
                int cn = cbase + j * 8 + g4;
                uint32_t b0 = Ws[kk + t4][cn];
                uint32_t b1 = Ws[kk + t4 + 4][cn];
#pragma unroll
                for (int i = 0; i < 2; i++) mma16n8k8(acc[i][j], a[i], b0, b1);
            }
        }
        __syncthreads();
    }

    // epilogue: bias + relu, fragment-direct stores
#pragma unroll
    for (int j = 0; j < 8; j++) {
        int col = cbase + j * 8 + t4 * 2;
        float bx = __ldg(&bias[col]);
        float by = __ldg(&bias[col + 1]);
#pragma unroll
        for (int i = 0; i < 2; i++) {
            int r0 = block_row + rbase + i * 16 + g4;
            if (r0 < NN) {
                float2 o0 = make_float2(fmaxf(acc[i][j][0] + bx, 0.f),
                                        fmaxf(acc[i][j][1] + by, 0.f));
                *(float2*)&C[(long long)r0 * 128 + col] = o0;
            }
            if (r0 + 8 < NN) {
                float2 o1 = make_float2(fmaxf(acc[i][j][2] + bx, 0.f),
                                        fmaxf(acc[i][j][3] + by, 0.f));
                *(float2*)&C[(long long)(r0 + 8) * 128 + col] = o1;
            }
        }
    }
}

// ---------------- global mean pool ----------------
__global__ void pool_kernel(const float* __restrict__ h, const void* __restrict__ batch,
                            float* __restrict__ pool, float* __restrict__ cnt) {
    long long idx = (long long)blockIdx.x * blockDim.x + threadIdx.x;
    if (idx >= (long long)NN * 32) return;
    long long n = idx >> 5;
    int c4 = (int)(idx & 31) * 4;
    long long g = load_idx(batch, n, g_is64);
    float4 v = *(const float4*)&h[n * 128 + c4];
    red_add_v4(&pool[g * 128 + c4], v.x, v.y, v.z, v.w);
    if (c4 == 0) atomicAdd(&cnt[g], 1.0f);
}
__global__ void finalize_kernel(const float* __restrict__ pool, const float* __restrict__ cnt,
                                float* __restrict__ out) {
    int i = blockIdx.x * blockDim.x + threadIdx.x;
    if (i < NG * 128) out[i] = pool[i] / fmaxf(cnt[i >> 7], 1.0f);
}

// ---------------- launch ----------------
extern "C" void kernel_launch(void* const* d_in, const int* in_sizes, int n_in,
                              void* d_out, int out_size) {
    const float* x     = (const float*)d_in[0];
    const void*  ei    = d_in[1];
    const float* attr  = (const float*)d_in[2];
    const void*  batch = d_in[3];
    const float* el1_w = (const float*)d_in[4];
    const float* el1_b = (const float*)d_in[5];
    const float* w1a   = (const float*)d_in[6];
    const float* b1a   = (const float*)d_in[7];
    const float* w1b   = (const float*)d_in[8];
    const float* b1b   = (const float*)d_in[9];
    const float* el2_w = (const float*)d_in[10];
    const float* el2_b = (const float*)d_in[11];
    const float* w2a   = (const float*)d_in[12];
    const float* b2a   = (const float*)d_in[13];
    const float* w2b   = (const float*)d_in[14];
    const float* b2b   = (const float*)d_in[15];
    float* out = (float*)d_out;

    float *agg, *mid, *h, *pool, *cnt;
    cudaGetSymbolAddress((void**)&agg,  g_agg);
    cudaGetSymbolAddress((void**)&mid,  g_mid);
    cudaGetSymbolAddress((void**)&h,    g_h);
    cudaGetSymbolAddress((void**)&pool, g_pool);
    cudaGetSymbolAddress((void**)&cnt,  g_cnt);

    detect_kernel<<<1, 32>>>((const int*)ei);

    const int ggrid = (NN + 127) / 128;

    // ---- layer 1 (CH=64) ----
    {
        long long n4 = (long long)NN * 64 / 4;
        copy_kernel<<<(int)((n4 + 255) / 256), 256>>>(x, agg, n4);
        long long t = (long long)NE * 16;
        edge_msg_kernel<64><<<(int)((t + 255) / 256), 256>>>(x, ei, attr, el1_w, el1_b, agg);
    }
    mma_gemm_kernel<64><<<ggrid, 256>>>(agg, w1a, b1a, mid);
    mma_gemm_kernel<128><<<ggrid, 256>>>(mid, w1b, b1b, h);

    // ---- layer 2 (CH=128) ----
    {
        long long n4 = (long long)NN * 128 / 4;
        copy_kernel<<<(int)((n4 + 255) / 256), 256>>>(h, agg, n4);
        long long t = (long long)NE * 32;
        edge_msg_kernel<128><<<(int)((t + 255) / 256), 256>>>(h, ei, attr, el2_w, el2_b, agg);
    }
    mma_gemm_kernel<128><<<ggrid, 256>>>(agg, w2a, b2a, mid);
    mma_gemm_kernel<128><<<ggrid, 256>>>(mid, w2b, b2b, h);

    // ---- global mean pool ----
    zero_kernel<<<(NG * 128 / 4 + 255) / 256, 256>>>(pool, NG * 128 / 4);
    zero_kernel<<<1, 16>>>(cnt, NG / 4);
    {
        long long t = (long long)NN * 32;
        pool_kernel<<<(int)((t + 255) / 256), 256>>>(h, batch, pool, cnt);
    }
    finalize_kernel<<<(NG * 128 + 255) / 256, 256>>>(pool, cnt, out);
}

// round 5
// speedup vs baseline: 1.7835x; 1.4029x over previous
#include <cuda_runtime.h>
#include <cstdint>

#define NN 50000
#define NE 600000
#define NG 64

// ---------------- scratch (no allocations allowed) ----------------
__device__ float g_agg[(size_t)NN * 128];
__device__ float g_mid[(size_t)NN * 128];
__device__ float g_h  [(size_t)NN * 128];
__device__ float g_pool[NG * 128];
__device__ float g_cnt[NG];
__device__ int   g_is64;
// CSR scratch
__device__ int g_cntE[NN];
__device__ int g_rowptr[NN + 1];
__device__ int g_wofs[NN];
__device__ int g_eid[NE];
__device__ int g_bsum[128];

// ---------------- helpers ----------------
__device__ __forceinline__ void red_add_v4(float* addr, float a, float b, float c, float d) {
    asm volatile("red.global.add.v4.f32 [%0], {%1,%2,%3,%4};"
                 :: "l"(addr), "f"(a), "f"(b), "f"(c), "f"(d) : "memory");
}
__device__ __forceinline__ long long load_idx(const void* p, long long i, int is64) {
    if (is64) return ((const long long*)p)[i];
    return (long long)((const int*)p)[i];
}
__device__ __forceinline__ uint32_t f2tf32(float x) {
    uint32_t r;
    asm("cvt.rna.tf32.f32 %0, %1;" : "=r"(r) : "f"(x));
    return r;
}
__device__ __forceinline__ void mma16n8k8(float* c, const uint32_t* a, uint32_t b0, uint32_t b1) {
    asm volatile("mma.sync.aligned.m16n8k8.row.col.f32.tf32.tf32.f32 "
                 "{%0,%1,%2,%3}, {%4,%5,%6,%7}, {%8,%9}, {%0,%1,%2,%3};"
                 : "+f"(c[0]), "+f"(c[1]), "+f"(c[2]), "+f"(c[3])
                 : "r"(a[0]), "r"(a[1]), "r"(a[2]), "r"(a[3]), "r"(b0), "r"(b1));
}

__global__ void detect_kernel(const int* ei32) {
    int v = ei32[2 * threadIdx.x + 1] | ei32[2 * (threadIdx.x + 32) + 1];
    unsigned b = __ballot_sync(0xffffffffu, v != 0);
    if (threadIdx.x == 0) g_is64 = (b == 0) ? 1 : 0;
}
__global__ void zero_kernel(float* p, long long n4) {
    long long i = (long long)blockIdx.x * blockDim.x + threadIdx.x;
    if (i < n4) ((float4*)p)[i] = make_float4(0.f, 0.f, 0.f, 0.f);
}

// ---------------- CSR build (dst-binned) ----------------
__global__ void hist_kernel(const void* __restrict__ ei, int* __restrict__ cnt) {
    long long e = (long long)blockIdx.x * blockDim.x + threadIdx.x;
    if (e < NE) {
        long long dst = load_idx(ei, NE + e, g_is64);
        atomicAdd(&cnt[dst], 1);
    }
}
// per-block exclusive scan of counts (512 per block), block totals to bsum
__global__ void scan1_kernel(const int* __restrict__ cnt, int* __restrict__ rowptr,
                             int* __restrict__ bsum) {
    __shared__ int s[512];
    int tid = threadIdx.x;
    int i = blockIdx.x * 512 + tid;
    int v = (i < NN) ? cnt[i] : 0;
    s[tid] = v;
    __syncthreads();
    for (int ofs = 1; ofs < 512; ofs <<= 1) {
        int t = (tid >= ofs) ? s[tid - ofs] : 0;
        __syncthreads();
        s[tid] += t;
        __syncthreads();
    }
    if (i < NN) rowptr[i] = s[tid] - v;       // exclusive
    if (tid == 511) bsum[blockIdx.x] = s[511];
}
__global__ void scan2_kernel(int* __restrict__ bsum, int nb) {
    __shared__ int s[128];
    int tid = threadIdx.x;
    int v = (tid < nb) ? bsum[tid] : 0;
    s[tid] = v;
    __syncthreads();
    for (int ofs = 1; ofs < 128; ofs <<= 1) {
        int t = (tid >= ofs) ? s[tid - ofs] : 0;
        __syncthreads();
        s[tid] += t;
        __syncthreads();
    }
    if (tid < nb) bsum[tid] = s[tid] - v;     // exclusive
}
__global__ void scan3_kernel(int* __restrict__ rowptr, const int* __restrict__ bsum,
                             int* __restrict__ wofs) {
    int i = blockIdx.x * blockDim.x + threadIdx.x;
    if (i < NN) {
        int r = rowptr[i] + bsum[i >> 9];
        rowptr[i] = r;
        wofs[i] = r;
    }
    if (i == 0) rowptr[NN] = NE;
}
__global__ void scatter_kernel(const void* __restrict__ ei, int* __restrict__ wofs,
                               int* __restrict__ eid) {
    long long e = (long long)blockIdx.x * blockDim.x + threadIdx.x;
    if (e < NE) {
        long long dst = load_idx(ei, NE + e, g_is64);
        int pos = atomicAdd(&wofs[dst], 1);
        eid[pos] = (int)e;
    }
}

// ---------------- gather aggregation: one warp per node ----------------
// out[n] = x[n] + sum_{e: dst(e)=n} relu(x[src(e)] + attr(e) @ ew + eb)
template <int CH>
__global__ void agg_kernel(const float* __restrict__ x, const void* __restrict__ ei,
                           const float* __restrict__ attr,
                           const float* __restrict__ ew, const float* __restrict__ eb,
                           const int* __restrict__ rowptr, const int* __restrict__ eidp,
                           float* __restrict__ out) {
    const int VPL = CH / 32;
    int warp = (int)(((long long)blockIdx.x * blockDim.x + threadIdx.x) >> 5);
    int lane = threadIdx.x & 31;
    if (warp >= NN) return;
    int is64 = g_is64;
    int c0 = lane * VPL;
    float ew0[VPL], ew1[VPL], ew2[VPL], ebv[VPL], acc[VPL];
#pragma unroll
    for (int j = 0; j < VPL; j++) {
        ew0[j] = __ldg(&ew[c0 + j]);
        ew1[j] = __ldg(&ew[CH + c0 + j]);
        ew2[j] = __ldg(&ew[2 * CH + c0 + j]);
        ebv[j] = __ldg(&eb[c0 + j]);
        acc[j] = 0.f;
    }
    int beg = __ldg(&rowptr[warp]);
    int end = __ldg(&rowptr[warp + 1]);
    for (int p = beg; p < end; p++) {
        int e = __ldg(&eidp[p]);
        long long src = load_idx(ei, e, is64);
        float a0 = __ldg(&attr[(long long)e * 3 + 0]);
        float a1 = __ldg(&attr[(long long)e * 3 + 1]);
        float a2 = __ldg(&attr[(long long)e * 3 + 2]);
        float xv[VPL];
        if (VPL == 4) *(float4*)xv = *(const float4*)&x[src * CH + c0];
        else          *(float2*)xv = *(const float2*)&x[src * CH + c0];
#pragma unroll
        for (int j = 0; j < VPL; j++) {
            float ev = ebv[j] + a0 * ew0[j] + a1 * ew1[j] + a2 * ew2[j];
            acc[j] += fmaxf(xv[j] + ev, 0.f);
        }
    }
    float sv[VPL];
    if (VPL == 4) *(float4*)sv = *(const float4*)&x[(long long)warp * CH + c0];
    else          *(float2*)sv = *(const float2*)&x[(long long)warp * CH + c0];
#pragma unroll
    for (int j = 0; j < VPL; j++) sv[j] += acc[j];
    if (VPL == 4) *(float4*)&out[(long long)warp * CH + c0] = *(float4*)sv;
    else          *(float2*)&out[(long long)warp * CH + c0] = *(float2*)sv;
}

// ---------------- tf32 tensor-core GEMM via mma.sync ----------------
template <int K>
__global__ __launch_bounds__(256, 2) void mma_gemm_kernel(
    const float* __restrict__ A, const float* __restrict__ W,
    const float* __restrict__ bias, float* __restrict__ C) {
    __shared__ uint32_t As[128][20];
    __shared__ uint32_t Ws[16][136];
    const int tid = threadIdx.x, lane = tid & 31, wid = tid >> 5;
    const int block_row = blockIdx.x * 128;
    const int rbase = (wid & 3) * 32;
    const int cbase = (wid >> 2) * 64;
    const int g4 = lane >> 2;
    const int t4 = lane & 3;

    float acc[2][8][4];
#pragma unroll
    for (int i = 0; i < 2; i++)
#pragma unroll
        for (int j = 0; j < 8; j++)
#pragma unroll
            for (int q = 0; q < 4; q++) acc[i][j][q] = 0.f;

    for (int k0 = 0; k0 < K; k0 += 16) {
#pragma unroll
        for (int i = 0; i < 2; i++) {
            int idx = tid + i * 256;
            int r = idx >> 2;
            int kc = (idx & 3) * 4;
            int gr = block_row + r;
            float4 v = make_float4(0.f, 0.f, 0.f, 0.f);
            if (gr < NN) v = *(const float4*)&A[(long long)gr * K + k0 + kc];
            *(uint4*)&As[r][kc] = make_uint4(f2tf32(v.x), f2tf32(v.y), f2tf32(v.z), f2tf32(v.w));
        }
#pragma unroll
        for (int i = 0; i < 2; i++) {
            int idx = tid + i * 256;
            int r = idx >> 5;
            int cc = (idx & 31) * 4;
            float4 v = *(const float4*)&W[(long long)(k0 + r) * 128 + cc];
            *(uint4*)&Ws[r][cc] = make_uint4(f2tf32(v.x), f2tf32(v.y), f2tf32(v.z), f2tf32(v.w));
        }
        __syncthreads();
#pragma unroll
        for (int ks = 0; ks < 2; ks++) {
            const int kk = ks * 8;
            uint32_t a[2][4];
#pragma unroll
            for (int i = 0; i < 2; i++) {
                int r = rbase + i * 16 + g4;
                a[i][0] = As[r][kk + t4];
                a[i][1] = As[r + 8][kk + t4];
                a[i][2] = As[r][kk + t4 + 4];
                a[i][3] = As[r + 8][kk + t4 + 4];
            }
#pragma unroll
            for (int j = 0; j < 8; j++) {
                int cn = cbase + j * 8 + g4;
                uint32_t b0 = Ws[kk + t4][cn];
                uint32_t b1 = Ws[kk + t4 + 4][cn];
#pragma unroll
                for (int i = 0; i < 2; i++) mma16n8k8(acc[i][j], a[i], b0, b1);
            }
        }
        __syncthreads();
    }
#pragma unroll
    for (int j = 0; j < 8; j++) {
        int col = cbase + j * 8 + t4 * 2;
        float bx = __ldg(&bias[col]);
        float by = __ldg(&bias[col + 1]);
#pragma unroll
        for (int i = 0; i < 2; i++) {
            int r0 = block_row + rbase + i * 16 + g4;
            if (r0 < NN) {
                float2 o0 = make_float2(fmaxf(acc[i][j][0] + bx, 0.f),
                                        fmaxf(acc[i][j][1] + by, 0.f));
                *(float2*)&C[(long long)r0 * 128 + col] = o0;
            }
            if (r0 + 8 < NN) {
                float2 o1 = make_float2(fmaxf(acc[i][j][2] + bx, 0.f),
                                        fmaxf(acc[i][j][3] + by, 0.f));
                *(float2*)&C[(long long)(r0 + 8) * 128 + col] = o1;
            }
        }
    }
}

// ---------------- global mean pool ----------------
__global__ void pool_kernel(const float* __restrict__ h, const void* __restrict__ batch,
                            float* __restrict__ pool, float* __restrict__ cnt) {
    long long idx = (long long)blockIdx.x * blockDim.x + threadIdx.x;
    if (idx >= (long long)NN * 32) return;
    long long n = idx >> 5;
    int c4 = (int)(idx & 31) * 4;
    long long g = load_idx(batch, n, g_is64);
    float4 v = *(const float4*)&h[n * 128 + c4];
    red_add_v4(&pool[g * 128 + c4], v.x, v.y, v.z, v.w);
    if (c4 == 0) atomicAdd(&cnt[g], 1.0f);
}
__global__ void finalize_kernel(const float* __restrict__ pool, const float* __restrict__ cnt,
                                float* __restrict__ out) {
    int i = blockIdx.x * blockDim.x + threadIdx.x;
    if (i < NG * 128) out[i] = pool[i] / fmaxf(cnt[i >> 7], 1.0f);
}

// ---------------- launch ----------------
extern "C" void kernel_launch(void* const* d_in, const int* in_sizes, int n_in,
                              void* d_out, int out_size) {
    const float* x     = (const float*)d_in[0];
    const void*  ei    = d_in[1];
    const float* attr  = (const float*)d_in[2];
    const void*  batch = d_in[3];
    const float* el1_w = (const float*)d_in[4];
    const float* el1_b = (const float*)d_in[5];
    const float* w1a   = (const float*)d_in[6];
    const float* b1a   = (const float*)d_in[7];
    const float* w1b   = (const float*)d_in[8];
    const float* b1b   = (const float*)d_in[9];
    const float* el2_w = (const float*)d_in[10];
    const float* el2_b = (const float*)d_in[11];
    const float* w2a   = (const float*)d_in[12];
    const float* b2a   = (const float*)d_in[13];
    const float* w2b   = (const float*)d_in[14];
    const float* b2b   = (const float*)d_in[15];
    float* out = (float*)d_out;

    float *agg, *mid, *h, *pool, *cnt;
    int *cntE, *rowptr, *wofs, *eid, *bsum;
    cudaGetSymbolAddress((void**)&agg,  g_agg);
    cudaGetSymbolAddress((void**)&mid,  g_mid);
    cudaGetSymbolAddress((void**)&h,    g_h);
    cudaGetSymbolAddress((void**)&pool, g_pool);
    cudaGetSymbolAddress((void**)&cnt,  g_cnt);
    cudaGetSymbolAddress((void**)&cntE,   g_cntE);
    cudaGetSymbolAddress((void**)&rowptr, g_rowptr);
    cudaGetSymbolAddress((void**)&wofs,   g_wofs);
    cudaGetSymbolAddress((void**)&eid,    g_eid);
    cudaGetSymbolAddress((void**)&bsum,   g_bsum);

    detect_kernel<<<1, 32>>>((const int*)ei);

    // ---- CSR build (once; reused by both layers) ----
    const int NB = (NN + 511) / 512;   // 98
    zero_kernel<<<(NN / 4 + 255) / 256, 256>>>((float*)cntE, NN / 4);
    hist_kernel<<<(NE + 255) / 256, 256>>>(ei, cntE);
    scan1_kernel<<<NB, 512>>>(cntE, rowptr, bsum);
    scan2_kernel<<<1, 128>>>(bsum, NB);
    scan3_kernel<<<(NN + 255) / 256, 256>>>(rowptr, bsum, wofs);
    scatter_kernel<<<(NE + 255) / 256, 256>>>(ei, wofs, eid);

    const int ggrid = (NN + 127) / 128;
    const int agrid = (int)(((long long)NN * 32 + 255) / 256);

    // ---- layer 1 (CH=64) ----
    agg_kernel<64><<<agrid, 256>>>(x, ei, attr, el1_w, el1_b, rowptr, eid, agg);
    mma_gemm_kernel<64><<<ggrid, 256>>>(agg, w1a, b1a, mid);
    mma_gemm_kernel<128><<<ggrid, 256>>>(mid, w1b, b1b, h);

    // ---- layer 2 (CH=128) ----
    agg_kernel<128><<<agrid, 256>>>(h, ei, attr, el2_w, el2_b, rowptr, eid, agg);
    mma_gemm_kernel<128><<<ggrid, 256>>>(agg, w2a, b2a, mid);
    mma_gemm_kernel<128><<<ggrid, 256>>>(mid, w2b, b2b, h);

    // ---- global mean pool ----
    zero_kernel<<<(NG * 128 / 4 + 255) / 256, 256>>>(pool, NG * 128 / 4);
    zero_kernel<<<1, 16>>>(cnt, NG / 4);
    {
        long long t = (long long)NN * 32;
        pool_kernel<<<(int)((t + 255) / 256), 256>>>(h, batch, pool, cnt);
    }
    finalize_kernel<<<(NG * 128 + 255) / 256, 256>>>(pool, cnt, out);
}

// round 6
// speedup vs baseline: 2.1732x; 1.2185x over previous
#include <cuda_runtime.h>
#include <cstdint>

#define NN 50000
#define NE 600000
#define NG 64

// ---------------- scratch (no allocations allowed) ----------------
__device__ float g_agg[(size_t)NN * 128];
__device__ float g_h  [(size_t)NN * 128];
__device__ float g_pool[NG * 128];
__device__ float g_cnt[NG];
__device__ int   g_is64;
// CSR scratch
__device__ int    g_cntE[NN];
__device__ int    g_rowptr[NN + 1];
__device__ int    g_wofs[NN];
__device__ float4 g_erec[NE];      // {src(bitcast), a0, a1, a2} per dst-sorted slot
__device__ int    g_bsum[128];

// ---------------- helpers ----------------
__device__ __forceinline__ void red_add_v4(float* addr, float a, float b, float c, float d) {
    asm volatile("red.global.add.v4.f32 [%0], {%1,%2,%3,%4};"
                 :: "l"(addr), "f"(a), "f"(b), "f"(c), "f"(d) : "memory");
}
__device__ __forceinline__ long long load_idx(const void* p, long long i, int is64) {
    if (is64) return ((const long long*)p)[i];
    return (long long)((const int*)p)[i];
}
__device__ __forceinline__ uint32_t f2tf32(float x) {
    uint32_t r;
    asm("cvt.rna.tf32.f32 %0, %1;" : "=r"(r) : "f"(x));
    return r;
}
__device__ __forceinline__ void mma16n8k8(float* c, const uint32_t* a, uint32_t b0, uint32_t b1) {
    asm volatile("mma.sync.aligned.m16n8k8.row.col.f32.tf32.tf32.f32 "
                 "{%0,%1,%2,%3}, {%4,%5,%6,%7}, {%8,%9}, {%0,%1,%2,%3};"
                 : "+f"(c[0]), "+f"(c[1]), "+f"(c[2]), "+f"(c[3])
                 : "r"(a[0]), "r"(a[1]), "r"(a[2]), "r"(a[3]), "r"(b0), "r"(b1));
}

__global__ void detect_kernel(const int* ei32) {
    int v = ei32[2 * threadIdx.x + 1] | ei32[2 * (threadIdx.x + 32) + 1];
    unsigned b = __ballot_sync(0xffffffffu, v != 0);
    if (threadIdx.x == 0) g_is64 = (b == 0) ? 1 : 0;
}
__global__ void zero_kernel(float* p, long long n4) {
    long long i = (long long)blockIdx.x * blockDim.x + threadIdx.x;
    if (i < n4) ((float4*)p)[i] = make_float4(0.f, 0.f, 0.f, 0.f);
}

// ---------------- CSR build (dst-binned) ----------------
__global__ void hist_kernel(const void* __restrict__ ei, int* __restrict__ cnt) {
    long long e = (long long)blockIdx.x * blockDim.x + threadIdx.x;
    if (e < NE) {
        long long dst = load_idx(ei, NE + e, g_is64);
        atomicAdd(&cnt[dst], 1);
    }
}
__global__ void scan1_kernel(const int* __restrict__ cnt, int* __restrict__ rowptr,
                             int* __restrict__ bsum) {
    __shared__ int s[512];
    int tid = threadIdx.x;
    int i = blockIdx.x * 512 + tid;
    int v = (i < NN) ? cnt[i] : 0;
    s[tid] = v;
    __syncthreads();
    for (int ofs = 1; ofs < 512; ofs <<= 1) {
        int t = (tid >= ofs) ? s[tid - ofs] : 0;
        __syncthreads();
        s[tid] += t;
        __syncthreads();
    }
    if (i < NN) rowptr[i] = s[tid] - v;
    if (tid == 511) bsum[blockIdx.x] = s[511];
}
__global__ void scan2_kernel(int* __restrict__ bsum, int nb) {
    __shared__ int s[128];
    int tid = threadIdx.x;
    int v = (tid < nb) ? bsum[tid] : 0;
    s[tid] = v;
    __syncthreads();
    for (int ofs = 1; ofs < 128; ofs <<= 1) {
        int t = (tid >= ofs) ? s[tid - ofs] : 0;
        __syncthreads();
        s[tid] += t;
        __syncthreads();
    }
    if (tid < nb) bsum[tid] = s[tid] - v;
}
__global__ void scan3_kernel(int* __restrict__ rowptr, const int* __restrict__ bsum,
                             int* __restrict__ wofs) {
    int i = blockIdx.x * blockDim.x + threadIdx.x;
    if (i < NN) {
        int r = rowptr[i] + bsum[i >> 9];
        rowptr[i] = r;
        wofs[i] = r;
    }
    if (i == 0) rowptr[NN] = NE;
}
// scatter edge record {src, a0,a1,a2} into dst-sorted slot
__global__ void scatter_kernel(const void* __restrict__ ei, const float* __restrict__ attr,
                               int* __restrict__ wofs, float4* __restrict__ rec) {
    long long e = (long long)blockIdx.x * blockDim.x + threadIdx.x;
    if (e < NE) {
        int is64 = g_is64;
        long long dst = load_idx(ei, NE + e, is64);
        int src = (int)load_idx(ei, e, is64);
        int pos = atomicAdd(&wofs[dst], 1);
        float4 r;
        r.x = __int_as_float(src);
        r.y = __ldg(&attr[e * 3 + 0]);
        r.z = __ldg(&attr[e * 3 + 1]);
        r.w = __ldg(&attr[e * 3 + 2]);
        rec[pos] = r;
    }
}

// ---------------- gather aggregation: one warp per node ----------------
// out[n] = x[n] + sum_{e: dst(e)=n} relu(x[src(e)] + attr(e) @ ew + eb)
template <int CH>
__global__ void agg_kernel(const float* __restrict__ x, const float4* __restrict__ recs,
                           const float* __restrict__ ew, const float* __restrict__ eb,
                           const int* __restrict__ rowptr, float* __restrict__ out) {
    const int VPL = CH / 32;
    int warp = (int)(((long long)blockIdx.x * blockDim.x + threadIdx.x) >> 5);
    int lane = threadIdx.x & 31;
    if (warp >= NN) return;
    int c0 = lane * VPL;
    float ew0[VPL], ew1[VPL], ew2[VPL], ebv[VPL], acc[VPL];
#pragma unroll
    for (int j = 0; j < VPL; j++) {
        ew0[j] = __ldg(&ew[c0 + j]);
        ew1[j] = __ldg(&ew[CH + c0 + j]);
        ew2[j] = __ldg(&ew[2 * CH + c0 + j]);
        ebv[j] = __ldg(&eb[c0 + j]);
        acc[j] = 0.f;
    }
    int beg = __ldg(&rowptr[warp]);
    int end = __ldg(&rowptr[warp + 1]);
    int p = beg;
    for (; p + 1 < end; p += 2) {
        float4 r0 = __ldg(&recs[p]);
        float4 r1 = __ldg(&recs[p + 1]);
        long long s0 = (long long)__float_as_int(r0.x);
        long long s1 = (long long)__float_as_int(r1.x);
        float x0[VPL], x1[VPL];
        if (VPL == 4) {
            *(float4*)x0 = *(const float4*)&x[s0 * CH + c0];
            *(float4*)x1 = *(const float4*)&x[s1 * CH + c0];
        } else {
            *(float2*)x0 = *(const float2*)&x[s0 * CH + c0];
            *(float2*)x1 = *(const float2*)&x[s1 * CH + c0];
        }
#pragma unroll
        for (int j = 0; j < VPL; j++) {
            float e0 = ebv[j] + r0.y * ew0[j] + r0.z * ew1[j] + r0.w * ew2[j];
            float e1 = ebv[j] + r1.y * ew0[j] + r1.z * ew1[j] + r1.w * ew2[j];
            acc[j] += fmaxf(x0[j] + e0, 0.f) + fmaxf(x1[j] + e1, 0.f);
        }
    }
    if (p < end) {
        float4 r0 = __ldg(&recs[p]);
        long long s0 = (long long)__float_as_int(r0.x);
        float x0[VPL];
        if (VPL == 4) *(float4*)x0 = *(const float4*)&x[s0 * CH + c0];
        else          *(float2*)x0 = *(const float2*)&x[s0 * CH + c0];
#pragma unroll
        for (int j = 0; j < VPL; j++) {
            float e0 = ebv[j] + r0.y * ew0[j] + r0.z * ew1[j] + r0.w * ew2[j];
            acc[j] += fmaxf(x0[j] + e0, 0.f);
        }
    }
    float sv[VPL];
    if (VPL == 4) *(float4*)sv = *(const float4*)&x[(long long)warp * CH + c0];
    else          *(float2*)sv = *(const float2*)&x[(long long)warp * CH + c0];
#pragma unroll
    for (int j = 0; j < VPL; j++) sv[j] += acc[j];
    if (VPL == 4) *(float4*)&out[(long long)warp * CH + c0] = *(float4*)sv;
    else          *(float2*)&out[(long long)warp * CH + c0] = *(float2*)sv;
}

// ---------------- fused 2-GEMM node MLP (tf32 mma.sync) ----------------
// C = relu( relu(A @ W1 + b1) @ W2 + b2 ), A:[N,K1], W1:[K1,128], W2:[128,128]
// Mid tile (128x128, tf32) lives in SMEM between the two GEMMs.
template <int K1>
__global__ __launch_bounds__(256, 2) void fused_mlp_kernel(
    const float* __restrict__ A, const float* __restrict__ W1, const float* __restrict__ b1,
    const float* __restrict__ W2, const float* __restrict__ b2, float* __restrict__ C) {
    extern __shared__ uint32_t sm[];
    uint32_t (*As)[20]   = (uint32_t(*)[20])sm;                    // 128x20
    uint32_t (*Ws)[136]  = (uint32_t(*)[136])(sm + 128 * 20);      // 16x136
    uint32_t (*Mid)[132] = (uint32_t(*)[132])(sm + 128 * 20 + 16 * 136);  // 128x132

    const int tid = threadIdx.x, lane = tid & 31, wid = tid >> 5;
    const int block_row = blockIdx.x * 128;
    const int rbase = (wid & 3) * 32;
    const int cbase = (wid >> 2) * 64;
    const int g4 = lane >> 2;
    const int t4 = lane & 3;

    float acc[2][8][4];
#pragma unroll
    for (int i = 0; i < 2; i++)
#pragma unroll
        for (int j = 0; j < 8; j++)
#pragma unroll
            for (int q = 0; q < 4; q++) acc[i][j][q] = 0.f;

    // ---------- GEMM 1: acc = A @ W1 ----------
    for (int k0 = 0; k0 < K1; k0 += 16) {
#pragma unroll
        for (int i = 0; i < 2; i++) {
            int idx = tid + i * 256;
            int r = idx >> 2;
            int kc = (idx & 3) * 4;
            int gr = block_row + r;
            float4 v = make_float4(0.f, 0.f, 0.f, 0.f);
            if (gr < NN) v = *(const float4*)&A[(long long)gr * K1 + k0 + kc];
            *(uint4*)&As[r][kc] = make_uint4(f2tf32(v.x), f2tf32(v.y), f2tf32(v.z), f2tf32(v.w));
        }
#pragma unroll
        for (int i = 0; i < 2; i++) {
            int idx = tid + i * 256;
            int r = idx >> 5;
            int cc = (idx & 31) * 4;
            float4 v = *(const float4*)&W1[(long long)(k0 + r) * 128 + cc];
            *(uint4*)&Ws[r][cc] = make_uint4(f2tf32(v.x), f2tf32(v.y), f2tf32(v.z), f2tf32(v.w));
        }
        __syncthreads();
#pragma unroll
        for (int ks = 0; ks < 2; ks++) {
            const int kk = ks * 8;
            uint32_t a[2][4];
#pragma unroll
            for (int i = 0; i < 2; i++) {
                int r = rbase + i * 16 + g4;
                a[i][0] = As[r][kk + t4];
                a[i][1] = As[r + 8][kk + t4];
                a[i][2] = As[r][kk + t4 + 4];
                a[i][3] = As[r + 8][kk + t4 + 4];
            }
#pragma unroll
            for (int j = 0; j < 8; j++) {
                int cn = cbase + j * 8 + g4;
                uint32_t b0 = Ws[kk + t4][cn];
                uint32_t b1 = Ws[kk + t4 + 4][cn];
#pragma unroll
                for (int i = 0; i < 2; i++) mma16n8k8(acc[i][j], a[i], b0, b1);
            }
        }
        __syncthreads();
    }
    // epilogue 1: Mid = tf32(relu(acc + b1)), stays in SMEM
#pragma unroll
    for (int j = 0; j < 8; j++) {
        int col = cbase + j * 8 + t4 * 2;
        float bx = __ldg(&b1[col]);
        float by = __ldg(&b1[col + 1]);
#pragma unroll
        for (int i = 0; i < 2; i++) {
            int r0 = rbase + i * 16 + g4;
            Mid[r0][col]         = f2tf32(fmaxf(acc[i][j][0] + bx, 0.f));
            Mid[r0][col + 1]     = f2tf32(fmaxf(acc[i][j][1] + by, 0.f));
            Mid[r0 + 8][col]     = f2tf32(fmaxf(acc[i][j][2] + bx, 0.f));
            Mid[r0 + 8][col + 1] = f2tf32(fmaxf(acc[i][j][3] + by, 0.f));
            acc[i][j][0] = 0.f; acc[i][j][1] = 0.f; acc[i][j][2] = 0.f; acc[i][j][3] = 0.f;
        }
    }
    __syncthreads();

    // ---------- GEMM 2: acc = Mid @ W2 (Mid from SMEM) ----------
    for (int k0 = 0; k0 < 128; k0 += 16) {
#pragma unroll
        for (int i = 0; i < 2; i++) {
            int idx = tid + i * 256;
            int r = idx >> 5;
            int cc = (idx & 31) * 4;
            float4 v = *(const float4*)&W2[(long long)(k0 + r) * 128 + cc];
            *(uint4*)&Ws[r][cc] = make_uint4(f2tf32(v.x), f2tf32(v.y), f2tf32(v.z), f2tf32(v.w));
        }
        __syncthreads();
#pragma unroll
        for (int ks = 0; ks < 2; ks++) {
            const int kk = ks * 8;
            uint32_t a[2][4];
#pragma unroll
            for (int i = 0; i < 2; i++) {
                int r = rbase + i * 16 + g4;
                a[i][0] = Mid[r][k0 + kk + t4];
                a[i][1] = Mid[r + 8][k0 + kk + t4];
                a[i][2] = Mid[r][k0 + kk + t4 + 4];
                a[i][3] = Mid[r + 8][k0 + kk + t4 + 4];
            }
#pragma unroll
            for (int j = 0; j < 8; j++) {
                int cn = cbase + j * 8 + g4;
                uint32_t b0 = Ws[kk + t4][cn];
                uint32_t b1 = Ws[kk + t4 + 4][cn];
#pragma unroll
                for (int i = 0; i < 2; i++) mma16n8k8(acc[i][j], a[i], b0, b1);
            }
        }
        __syncthreads();
    }
    // epilogue 2: C = relu(acc + b2)
#pragma unroll
    for (int j = 0; j < 8; j++) {
        int col = cbase + j * 8 + t4 * 2;
        float bx = __ldg(&b2[col]);
        float by = __ldg(&b2[col + 1]);
#pragma unroll
        for (int i = 0; i < 2; i++) {
            int r0 = block_row + rbase + i * 16 + g4;
            if (r0 < NN) {
                float2 o0 = make_float2(fmaxf(acc[i][j][0] + bx, 0.f),
                                        fmaxf(acc[i][j][1] + by, 0.f));
                *(float2*)&C[(long long)r0 * 128 + col] = o0;
            }
            if (r0 + 8 < NN) {
                float2 o1 = make_float2(fmaxf(acc[i][j][2] + bx, 0.f),
                                        fmaxf(acc[i][j][3] + by, 0.f));
                *(float2*)&C[(long long)(r0 + 8) * 128 + col] = o1;
            }
        }
    }
}

// ---------------- global mean pool ----------------
__global__ void pool_kernel(const float* __restrict__ h, const void* __restrict__ batch,
                            float* __restrict__ pool, float* __restrict__ cnt) {
    long long idx = (long long)blockIdx.x * blockDim.x + threadIdx.x;
    if (idx >= (long long)NN * 32) return;
    long long n = idx >> 5;
    int c4 = (int)(idx & 31) * 4;
    long long g = load_idx(batch, n, g_is64);
    float4 v = *(const float4*)&h[n * 128 + c4];
    red_add_v4(&pool[g * 128 + c4], v.x, v.y, v.z, v.w);
    if (c4 == 0) atomicAdd(&cnt[g], 1.0f);
}
__global__ void finalize_kernel(const float* __restrict__ pool, const float* __restrict__ cnt,
                                float* __restrict__ out) {
    int i = blockIdx.x * blockDim.x + threadIdx.x;
    if (i < NG * 128) out[i] = pool[i] / fmaxf(cnt[i >> 7], 1.0f);
}

// ---------------- launch ----------------
extern "C" void kernel_launch(void* const* d_in, const int* in_sizes, int n_in,
                              void* d_out, int out_size) {
    const float* x     = (const float*)d_in[0];
    const void*  ei    = d_in[1];
    const float* attr  = (const float*)d_in[2];
    const void*  batch = d_in[3];
    const float* el1_w = (const float*)d_in[4];
    const float* el1_b = (const float*)d_in[5];
    const float* w1a   = (const float*)d_in[6];
    const float* b1a   = (const float*)d_in[7];
    const float* w1b   = (const float*)d_in[8];
    const float* b1b   = (const float*)d_in[9];
    const float* el2_w = (const float*)d_in[10];
    const float* el2_b = (const float*)d_in[11];
    const float* w2a   = (const float*)d_in[12];
    const float* b2a   = (const float*)d_in[13];
    const float* w2b   = (const float*)d_in[14];
    const float* b2b   = (const float*)d_in[15];
    float* out = (float*)d_out;

    float *agg, *h, *pool, *cnt;
    int *cntE, *rowptr, *wofs, *bsum;
    float4* erec;
    cudaGetSymbolAddress((void**)&agg,  g_agg);
    cudaGetSymbolAddress((void**)&h,    g_h);
    cudaGetSymbolAddress((void**)&pool, g_pool);
    cudaGetSymbolAddress((void**)&cnt,  g_cnt);
    cudaGetSymbolAddress((void**)&cntE,   g_cntE);
    cudaGetSymbolAddress((void**)&rowptr, g_rowptr);
    cudaGetSymbolAddress((void**)&wofs,   g_wofs);
    cudaGetSymbolAddress((void**)&erec,   g_erec);
    cudaGetSymbolAddress((void**)&bsum,   g_bsum);

    const int SMF = (128 * 20 + 16 * 136 + 128 * 132) * 4;   // 86528 B
    cudaFuncSetAttribute(fused_mlp_kernel<64>,  cudaFuncAttributeMaxDynamicSharedMemorySize, SMF);
    cudaFuncSetAttribute(fused_mlp_kernel<128>, cudaFuncAttributeMaxDynamicSharedMemorySize, SMF);

    detect_kernel<<<1, 32>>>((const int*)ei);

    // ---- CSR build (once; reused by both layers) ----
    const int NB = (NN + 511) / 512;
    zero_kernel<<<(NN / 4 + 255) / 256, 256>>>((float*)cntE, NN / 4);
    hist_kernel<<<(NE + 255) / 256, 256>>>(ei, cntE);
    scan1_kernel<<<NB, 512>>>(cntE, rowptr, bsum);
    scan2_kernel<<<1, 128>>>(bsum, NB);
    scan3_kernel<<<(NN + 255) / 256, 256>>>(rowptr, bsum, wofs);
    scatter_kernel<<<(NE + 255) / 256, 256>>>(ei, attr, wofs, erec);

    const int ggrid = (NN + 127) / 128;
    const int agrid = (int)(((long long)NN * 32 + 255) / 256);

    // ---- layer 1 ----
    agg_kernel<64><<<agrid, 256>>>(x, erec, el1_w, el1_b, rowptr, agg);
    fused_mlp_kernel<64><<<ggrid, 256, SMF>>>(agg, w1a, b1a, w1b, b1b, h);

    // ---- layer 2 ----
    agg_kernel<128><<<agrid, 256>>>(h, erec, el2_w, el2_b, rowptr, agg);
    fused_mlp_kernel<128><<<ggrid, 256, SMF>>>(agg, w2a, b2a, w2b, b2b, h);

    // ---- global mean pool ----
    zero_kernel<<<(NG * 128 / 4 + 255) / 256, 256>>>(pool, NG * 128 / 4);
    zero_kernel<<<1, 16>>>(cnt, NG / 4);
    {
        long long t = (long long)NN * 32;
        pool_kernel<<<(int)((t + 255) / 256), 256>>>(h, batch, pool, cnt);
    }
    finalize_kernel<<<(NG * 128 + 255) / 256, 256>>>(pool, cnt, out);
}